// round 2
// baseline (speedup 1.0000x reference)
#include <cuda_runtime.h>
#include <cstdint>

#define T_LEN   16384
#define B_SZ    16
#define TILE    128
#define NTH     320
#define STRIDE  176
#define SLOPE_F 0.22916666666666666f
#define MUS_N   (B_SZ * (T_LEN - 32))

// -------- device scratch (no allocations allowed) --------
__device__ __align__(16) float g_wmid[3 * 2 * 64 * 64];  // [l][k][i][c]
__device__ __align__(16) float g_w4[2 * 64 * 8];         // [k][i][c]
__device__ __align__(16) float g_mus[B_SZ * T_LEN];

__device__ __forceinline__ float rrelu(float v) { return v >= 0.f ? v : v * SLOPE_F; }

// -------- weight reorder: cw[c][i][k] -> [k][i][c] --------
__global__ void reorder_kernel(const float* __restrict__ cw1, const float* __restrict__ cw2,
                               const float* __restrict__ cw3, const float* __restrict__ cw4) {
    int idx = blockIdx.x * blockDim.x + threadIdx.x;
    if (idx < 3 * 8192) {
        int l = idx / 8192, r = idx % 8192;
        int k = r / 4096, r2 = r % 4096;
        int i = r2 / 64, c = r2 % 64;
        const float* src = (l == 0) ? cw1 : (l == 1) ? cw2 : cw3;
        g_wmid[idx] = src[(c * 64 + i) * 2 + k];
    } else if (idx < 3 * 8192 + 1024) {
        int r = idx - 3 * 8192;
        int k = r / 512, r2 = r % 512;
        int i = r2 / 8, c = r2 % 8;
        g_w4[r] = cw4[(c * 64 + i) * 2 + k];
    }
}

// -------- middle conv layer (64 -> 64, K=2, dilation D) --------
template <int D>
__device__ __forceinline__ void conv_mid(const float* __restrict__ in, float* __restrict__ outb,
                                         const float* __restrict__ w, const float* __restrict__ bias,
                                         int tid) {
    const int cb = (tid & 15) * 4;
    const int j0 = (tid >> 4) * 8;
    float bv[4];
#pragma unroll
    for (int c = 0; c < 4; c++) bv[c] = __ldg(bias + cb + c);
    float acc[4][8];
#pragma unroll
    for (int c = 0; c < 4; c++)
#pragma unroll
        for (int u = 0; u < 8; u++) acc[c][u] = bv[c];

    const float* inp = in + j0;
#pragma unroll 4
    for (int i = 0; i < 64; i++) {
        float4 w0 = __ldg(reinterpret_cast<const float4*>(w + i * 64 + cb));
        float4 w1 = __ldg(reinterpret_cast<const float4*>(w + 4096 + i * 64 + cb));
        const float4* rp = reinterpret_cast<const float4*>(inp + i * STRIDE);
        float4 a0 = rp[0], a1 = rp[1], a2 = rp[2], a3 = rp[3];
        float a[16] = {a0.x, a0.y, a0.z, a0.w, a1.x, a1.y, a1.z, a1.w,
                       a2.x, a2.y, a2.z, a2.w, a3.x, a3.y, a3.z, a3.w};
        float wk0[4] = {w0.x, w0.y, w0.z, w0.w};
        float wk1[4] = {w1.x, w1.y, w1.z, w1.w};
#pragma unroll
        for (int c = 0; c < 4; c++)
#pragma unroll
            for (int u = 0; u < 8; u++)
                acc[c][u] += wk0[c] * a[u] + wk1[c] * a[u + D];
    }
#pragma unroll
    for (int c = 0; c < 4; c++)
#pragma unroll
        for (int u = 0; u < 8; u++)
            outb[(cb + c) * STRIDE + j0 + u] = rrelu(acc[c][u]);
}

// -------- main fused kernel: conv stack + gumbel softmax + MLP --------
__global__ __launch_bounds__(NTH, 2)
void fused_kernel(const float* __restrict__ x,
                  const float* __restrict__ cw0, const float* __restrict__ cb0,
                  const float* __restrict__ cb1, const float* __restrict__ cb2,
                  const float* __restrict__ cb3, const float* __restrict__ cb4,
                  const float* __restrict__ mw0, const float* __restrict__ mb0,
                  const float* __restrict__ mw1, const float* __restrict__ mb1,
                  const float* __restrict__ mw2, const float* __restrict__ mb2,
                  const float* __restrict__ gumbel,
                  float* __restrict__ out_z) {
    extern __shared__ float sm[];
    float* xs   = sm;                     // 176
    float* bufA = sm + 176;               // 64*176
    float* bufB = bufA + 64 * STRIDE;     // 64*176
    float* hs   = bufB + 64 * STRIDE;     // 8*132
    float* mw0s = hs + 8 * 132;           // 256
    float* mw1s = mw0s + 256;             // 256
    float* mw2s = mw1s + 256;             // 16
    float* mb0s = mw2s + 16;              // 16
    float* mb1s = mb0s + 16;              // 16
    float* mb2s = mb1s + 16;              // 1

    const int tid = threadIdx.x;
    const int b   = blockIdx.y;
    const int t0  = blockIdx.x * TILE;

    // x tile (with left zero padding of 31)
    for (int j = tid; j < 176; j += NTH) {
        int g = t0 + j - 31;
        xs[j] = (g >= 0 && g < T_LEN) ? __ldg(x + (size_t)b * T_LEN + g) : 0.f;
    }
    // zero padding columns [160,176) of both buffers
    for (int idx = tid; idx < 64 * 16; idx += NTH) {
        int r = idx >> 4, c = 160 + (idx & 15);
        bufA[r * STRIDE + c] = 0.f;
        bufB[r * STRIDE + c] = 0.f;
    }
    // MLP weights to smem
    for (int k = tid; k < 256; k += NTH) { mw0s[k] = __ldg(mw0 + k); mw1s[k] = __ldg(mw1 + k); }
    if (tid < 16) { mw2s[tid] = mw2[tid]; mb0s[tid] = mb0[tid]; mb1s[tid] = mb1[tid]; }
    if (tid == 0) mb2s[0] = mb2[0];
    __syncthreads();

    // layer 0: 1 -> 64, d=1
    {
        const int cb = (tid & 15) * 4;
        const int j0 = (tid >> 4) * 8;
        float w0c[4], w1c[4], bc[4];
#pragma unroll
        for (int c = 0; c < 4; c++) {
            w0c[c] = __ldg(cw0 + (cb + c) * 2);
            w1c[c] = __ldg(cw0 + (cb + c) * 2 + 1);
            bc[c]  = __ldg(cb0 + cb + c);
        }
        float xv[9];
#pragma unroll
        for (int u = 0; u < 9; u++) xv[u] = xs[j0 + u];
#pragma unroll
        for (int c = 0; c < 4; c++)
#pragma unroll
            for (int u = 0; u < 8; u++)
                bufA[(cb + c) * STRIDE + j0 + u] = rrelu(bc[c] + w0c[c] * xv[u] + w1c[c] * xv[u + 1]);
    }
    __syncthreads();

    conv_mid<2>(bufA, bufB, g_wmid,         cb1, tid); __syncthreads();
    conv_mid<4>(bufB, bufA, g_wmid + 8192,  cb2, tid); __syncthreads();
    conv_mid<8>(bufA, bufB, g_wmid + 16384, cb3, tid); __syncthreads();

    // layer 4: 64 -> 8, d=16
    if (tid < 256) {
        const int c  = tid & 7;
        const int j0 = (tid >> 3) * 4;
        float bv = __ldg(cb4 + c);
        float acc0 = bv, acc1 = bv, acc2 = bv, acc3 = bv;
        const float* inp = bufB + j0;
#pragma unroll 4
        for (int i = 0; i < 64; i++) {
            float wa = __ldg(g_w4 + i * 8 + c);
            float wb = __ldg(g_w4 + 512 + i * 8 + c);
            float4 a  = *reinterpret_cast<const float4*>(inp + i * STRIDE);
            float4 bb = *reinterpret_cast<const float4*>(inp + i * STRIDE + 16);
            acc0 += wa * a.x + wb * bb.x;
            acc1 += wa * a.y + wb * bb.y;
            acc2 += wa * a.z + wb * bb.z;
            acc3 += wa * a.w + wb * bb.w;
        }
        hs[c * 132 + j0 + 0] = rrelu(acc0);
        hs[c * 132 + j0 + 1] = rrelu(acc1);
        hs[c * 132 + j0 + 2] = rrelu(acc2);
        hs[c * 132 + j0 + 3] = rrelu(acc3);
    }
    __syncthreads();

    // gumbel softmax + MLP + mus
    if (tid < TILE) {
        const int j = tid;
        const int t = t0 + j;
        float l[8], gmb[8];
        const float4* gp = reinterpret_cast<const float4*>(gumbel + ((size_t)b * T_LEN + t) * 8);
        float4 g0 = __ldg(gp), g1 = __ldg(gp + 1);
        gmb[0] = g0.x; gmb[1] = g0.y; gmb[2] = g0.z; gmb[3] = g0.w;
        gmb[4] = g1.x; gmb[5] = g1.y; gmb[6] = g1.z; gmb[7] = g1.w;
#pragma unroll
        for (int r = 0; r < 8; r++) l[r] = hs[r * 132 + j];
        float a[8], mx = -1e30f;
#pragma unroll
        for (int r = 0; r < 8; r++) { a[r] = (l[r] + gmb[r]) * 10.f; mx = fmaxf(mx, a[r]); }
        float e[8], s = 0.f;
#pragma unroll
        for (int r = 0; r < 8; r++) { e[r] = __expf(a[r] - mx); s += e[r]; }
        float inv = 1.f / s;
        float z[8];
#pragma unroll
        for (int r = 0; r < 8; r++) {
            z[r] = e[r] * inv;
            out_z[((size_t)b * 8 + r) * T_LEN + t] = z[r];
        }
        float v[16];
#pragma unroll
        for (int r = 0; r < 8; r++) { v[r] = z[r]; v[8 + r] = l[r]; }
        float m1[16];
#pragma unroll
        for (int o = 0; o < 16; o++) {
            float s2 = mb0s[o];
#pragma unroll
            for (int ci = 0; ci < 16; ci++) s2 += mw0s[o * 16 + ci] * v[ci];
            m1[o] = rrelu(s2);
        }
        float m2[16];
#pragma unroll
        for (int o = 0; o < 16; o++) {
            float s2 = mb1s[o];
#pragma unroll
            for (int ci = 0; ci < 16; ci++) s2 += mw1s[o * 16 + ci] * m1[ci];
            m2[o] = rrelu(s2);
        }
        float mu = mb2s[0];
#pragma unroll
        for (int ci = 0; ci < 16; ci++) mu += mw2s[ci] * m2[ci];
        g_mus[(size_t)b * T_LEN + t] = mu;
    }
}

// -------- epilogue: windowed Fisher correction --------
__global__ __launch_bounds__(256)
void final_kernel(const float* __restrict__ x,
                  const float* __restrict__ sqrt_cov,
                  const float* __restrict__ fish,
                  const float* __restrict__ z_all,
                  float* __restrict__ out_mus) {
    __shared__ float xsm[288], msm[288], fsh[256], scs[8];
    const int tid = threadIdx.x;
    const int b   = blockIdx.y;
    const int p0  = blockIdx.x * 256;

    for (int i = tid; i < 288; i += 256) {
        int g = p0 + i;
        bool ok = g < T_LEN;
        xsm[i] = ok ? __ldg(x + (size_t)b * T_LEN + g) : 0.f;
        msm[i] = ok ? g_mus[(size_t)b * T_LEN + g] : 0.f;
    }
    if (tid < 256) fsh[tid] = __ldg(fish + tid);
    if (tid < 8)   scs[tid] = __ldg(sqrt_cov + tid);
    __syncthreads();

    const int p = p0 + tid;
    if (p < T_LEN - 32) {
        const int tau = p + 32;
        float z[8], cov = 0.f;
#pragma unroll
        for (int r = 0; r < 8; r++) {
            z[r] = __ldg(z_all + ((size_t)b * 8 + r) * T_LEN + tau);
            cov += z[r] * scs[r];
        }
        cov *= cov;
        float fj[32];
#pragma unroll
        for (int w = 0; w < 32; w++) fj[w] = 0.f;
#pragma unroll
        for (int r = 0; r < 8; r++)
#pragma unroll
            for (int w = 0; w < 32; w++)
                fj[w] += z[r] * fsh[r * 32 + w];
        float s = 0.f;
#pragma unroll
        for (int w = 0; w < 32; w++)
            s += fj[w] * (xsm[tid + w] - msm[tid + w]);
        out_mus[(size_t)b * (T_LEN - 32) + p] = msm[tid + 32] - cov * s;
    }
}

extern "C" void kernel_launch(void* const* d_in, const int* in_sizes, int n_in,
                              void* d_out, int out_size) {
    const float* x    = (const float*)d_in[0];
    const float* cw0  = (const float*)d_in[1];
    const float* cb0  = (const float*)d_in[2];
    const float* cw1  = (const float*)d_in[3];
    const float* cb1  = (const float*)d_in[4];
    const float* cw2  = (const float*)d_in[5];
    const float* cb2  = (const float*)d_in[6];
    const float* cw3  = (const float*)d_in[7];
    const float* cb3  = (const float*)d_in[8];
    const float* cw4  = (const float*)d_in[9];
    const float* cb4  = (const float*)d_in[10];
    const float* mw0  = (const float*)d_in[11];
    const float* mb0  = (const float*)d_in[12];
    const float* mw1  = (const float*)d_in[13];
    const float* mb1  = (const float*)d_in[14];
    const float* mw2  = (const float*)d_in[15];
    const float* mb2  = (const float*)d_in[16];
    const float* scv  = (const float*)d_in[17];
    const float* fish = (const float*)d_in[18];
    const float* gmb  = (const float*)d_in[19];

    float* out     = (float*)d_out;
    float* out_mus = out;            // [B, T-32]
    float* out_z   = out + MUS_N;    // [B, 8, T]

    const int smem_bytes = (176 + 2 * 64 * STRIDE + 8 * 132 + 256 * 2 + 16 * 3 + 1) * 4;
    cudaFuncSetAttribute(fused_kernel, cudaFuncAttributeMaxDynamicSharedMemorySize, smem_bytes);

    reorder_kernel<<<(3 * 8192 + 1024 + 255) / 256, 256>>>(cw1, cw2, cw3, cw4);
    fused_kernel<<<dim3(T_LEN / TILE, B_SZ), NTH, smem_bytes>>>(
        x, cw0, cb0, cb1, cb2, cb3, cb4, mw0, mb0, mw1, mb1, mw2, mb2, gmb, out_z);
    final_kernel<<<dim3((T_LEN - 32 + 255) / 256, B_SZ), 256>>>(x, scv, fish, out_z, out_mus);
}